// round 4
// baseline (speedup 1.0000x reference)
#include <cuda_runtime.h>
#include <math.h>

#define LSEQ 2048
#define NST  64
#define HD   512
#define BSZ  16

// ------------- device scratch (static; no runtime allocation) -------------
__device__ float d_P[11 * 64 * 64];    // Abar^(2^k), k=0..10, row-major, lower-tri
__device__ float d_Bbar[64];
__device__ float d_W[LSEQ * 64];       // w[s][n]  = (Abar^s Bbar)[n]
__device__ float d_V[LSEQ * 64];       // v[t][n]  = (C Abar^{L-1-t})[n]
__device__ float d_K[LSEQ];            // K[l]     = C Abar^l Bbar

// ---------------- lower-triangular 64x64 matmul (smem) ----------------
__device__ __forceinline__ void trimm(const float* A, const float* B, float* T, int tid) {
    for (int e = tid; e < 4096; e += 256) {
        int i = e >> 6, j = e & 63;
        float acc = 0.0f;
        if (j <= i) {
            for (int k = j; k <= i; k++) acc = fmaf(A[i * 64 + k], B[k * 64 + j], acc);
        }
        T[e] = acc;
    }
}

// ---------- setup: A, expm(dt*A), Bbar, powers Abar^(2^k) ----------
__global__ void setup_kernel(const float* __restrict__ B_in, const float* __restrict__ logdt) {
    extern __shared__ float sm[];
    float* As = sm;           // original A
    float* Xs = sm + 4096;    // scaled dt*A
    float* Rs = sm + 8192;    // accumulator
    float* Ts = sm + 12288;   // temp
    __shared__ float colsum[64];
    __shared__ float rhs[64], bb[64];
    __shared__ int s_sh;
    int tid = threadIdx.x;

    double dt = exp((double)logdt[0]);
    for (int e = tid; e < 4096; e += 256) {
        int i = e >> 6, j = e & 63;
        float a = 0.0f, x = 0.0f;
        if (j <= i) {
            double pij = sqrt((1.0 + 2.0 * i) * (1.0 + 2.0 * j));
            double av = pij - (i == j ? (double)i : 0.0);
            a = (float)(-av);
            x = (float)(-av * dt);
        }
        As[e] = a; Xs[e] = x;
    }
    __syncthreads();
    if (tid < 64) {                               // column 1-norms of dt*A
        float ssum = 0.0f;
        for (int i = tid; i < 64; i++) ssum += fabsf(Xs[i * 64 + tid]);
        colsum[tid] = ssum;
    }
    __syncthreads();
    if (tid == 0) {
        float mx = 0.0f;
        for (int j = 0; j < 64; j++) mx = fmaxf(mx, colsum[j]);
        int s = 0; float v = mx;
        while (v > 1.0f && s < 30) { v *= 0.5f; s++; }
        s_sh = s;
    }
    __syncthreads();
    int s = s_sh;
    float scale = ldexpf(1.0f, -s);
    for (int e = tid; e < 4096; e += 256) Xs[e] *= scale;
    __syncthreads();

    // Taylor deg-14 Horner: R = I + X/14; for k=13..1: R = I + (X*R)/k
    for (int e = tid; e < 4096; e += 256) {
        int i = e >> 6, j = e & 63;
        Rs[e] = Xs[e] * (1.0f / 14.0f) + (i == j ? 1.0f : 0.0f);
    }
    __syncthreads();
    for (int k = 13; k >= 1; k--) {
        trimm(Xs, Rs, Ts, tid);
        __syncthreads();
        float inv = 1.0f / (float)k;
        for (int e = tid; e < 4096; e += 256) {
            int i = e >> 6, j = e & 63;
            Rs[e] = (j <= i ? Ts[e] * inv : 0.0f) + (i == j ? 1.0f : 0.0f);
        }
        __syncthreads();
    }
    for (int q = 0; q < s; q++) {                 // undo scaling: s squarings
        trimm(Rs, Rs, Ts, tid);
        __syncthreads();
        for (int e = tid; e < 4096; e += 256) Rs[e] = Ts[e];
        __syncthreads();
    }
    for (int e = tid; e < 4096; e += 256) d_P[e] = Rs[e];   // P0 = Abar
    __syncthreads();
    for (int k = 1; k < 11; k++) {                // Pk = P_{k-1}^2
        trimm(Rs, Rs, Ts, tid);
        __syncthreads();
        for (int e = tid; e < 4096; e += 256) {
            Rs[e] = Ts[e];
            d_P[k * 4096 + e] = Ts[e];
        }
        __syncthreads();
    }
    // rhs = (Abar - I) B ; Bbar = A^{-1} rhs  (forward substitution)
    if (tid < 64) {
        float acc = 0.0f;
        for (int j = 0; j < 64; j++) {
            float p = d_P[tid * 64 + j] - (tid == j ? 1.0f : 0.0f);
            acc = fmaf(p, B_in[j], acc);
        }
        rhs[tid] = acc;
    }
    __syncthreads();
    if (tid == 0) {
        for (int i = 0; i < 64; i++) {
            double acc = (double)rhs[i];
            for (int j = 0; j < i; j++) acc -= (double)As[i * 64 + j] * (double)bb[j];
            bb[i] = (float)(acc / (double)As[i * 64 + i]);
        }
    }
    __syncthreads();
    if (tid < 64) d_Bbar[tid] = bb[tid];
}

// ---- expand: w[s], v-row(s), K[s] via bit-product; block = s, 64 threads ----
__global__ void expand_kernel(const float* __restrict__ C_in) {
    int s = blockIdx.x;
    int t = threadIdx.x;
    __shared__ float xs[64], rs[64], prod[64];
    xs[t] = d_Bbar[t];
    rs[t] = C_in[t];
    __syncthreads();
    for (int k = 0; k < 11; k++) {
        if ((s >> k) & 1) {                        // uniform branch per block
            const float* P = d_P + k * 4096;
            float a = 0.0f, b = 0.0f;
            for (int j = 0; j <= t; j++) a = fmaf(P[t * 64 + j], xs[j], a);  // row t
            for (int i = t; i < 64; i++) b = fmaf(rs[i], P[i * 64 + t], b);  // col t
            __syncthreads();
            xs[t] = a; rs[t] = b;
            __syncthreads();
        }
    }
    d_W[s * 64 + t] = xs[t];
    d_V[(LSEQ - 1 - s) * 64 + t] = rs[t];          // v[t] = C Abar^{L-1-t}
    prod[t] = rs[t] * d_Bbar[t];
    __syncthreads();
    if (t == 0) {
        float acc = 0.0f;
        for (int j = 0; j < 64; j++) acc += prod[j];
        d_K[s] = acc;                               // K[s] = C Abar^s Bbar
    }
}

// ---------------- main fused chunked-scan kernel ----------------
// block = (b, 64-h tile). 32 sequential chunks of 64 timesteps; state X[n][h]
// lives in smem. Per chunk:
//   Y[i][h] = sum_n V[tb+i][n] X[n][h] + sum_{j<=i} K[L-1-(i-j)] U[j][h] + D U[i][h]
//   X[n][h] += sum_j W[tb+j][n] U[j][h]
__global__ void __launch_bounds__(256, 1)
main_kernel(const float* __restrict__ u, const float* __restrict__ Dp, float* __restrict__ y) {
    extern __shared__ float sm[];
    float* Us  = sm;           // [j][h]
    float* Ws  = sm + 4096;    // [j][n]
    float* VT  = sm + 8192;    // [n][i]  (V transposed)
    float* TzT = sm + 12288;   // [j][i]  TzT[j][i] = K[L-1-(i-j)], i>=j
    float* Xs  = sm + 16384;   // [n][h]  running state

    int tid = threadIdx.x;
    int b = blockIdx.x >> 3;
    int habs = (blockIdx.x & 7) << 6;
    float Dv = Dp[0];

    for (int e = tid; e < 4096; e += 256) {
        int j = e >> 6, i = e & 63;
        TzT[e] = (i >= j) ? d_K[LSEQ - 1 - (i - j)] : 0.0f;
        Xs[e] = 0.0f;
    }

    int tx = tid & 15, ty = tid >> 4;
    int h0 = tx << 2, i0 = ty << 2;                // i0 doubles as n0 in phase 2

    const float* ub = u + (size_t)b * LSEQ * HD + habs;
    float*       yb = y + (size_t)b * LSEQ * HD + habs;

    for (int c = 0; c < 32; c++) {
        int tb = c << 6;
        // ---- loads ----
        for (int f = tid; f < 1024; f += 256) {    // u tile [64 x 64], coalesced
            int j = f >> 4, q = f & 15;
            ((float4*)Us)[(j << 4) + q] =
                __ldg((const float4*)(ub + (size_t)(tb + j) * HD) + q);
        }
        {
            const float4* Wg = (const float4*)(d_W + (size_t)tb * 64);
            for (int f = tid; f < 1024; f += 256) ((float4*)Ws)[f] = __ldg(Wg + f);
        }
        {   // V slice transposed: VT[n][i] = d_V[(tb+i)*64+n]
            int ii = tid & 63, ng = tid >> 6;      // 4 groups x 16 n each
            const float* Vrow = d_V + (size_t)(tb + ii) * 64 + (ng << 4);
#pragma unroll
            for (int q2 = 0; q2 < 4; q2++) {
                float4 v = *(const float4*)(Vrow + (q2 << 2));
                int n0 = (ng << 4) + (q2 << 2);
                VT[(n0 + 0) * 64 + ii] = v.x;
                VT[(n0 + 1) * 64 + ii] = v.y;
                VT[(n0 + 2) * 64 + ii] = v.z;
                VT[(n0 + 3) * 64 + ii] = v.w;
            }
        }
        __syncthreads();

        // ---- phase 1: Y = V*X + Tz*U + D*U, write to gmem ----
        {
            float acc[4][4];
#pragma unroll
            for (int a = 0; a < 4; a++)
#pragma unroll
                for (int q = 0; q < 4; q++) acc[a][q] = 0.0f;
#pragma unroll 8
            for (int n = 0; n < 64; n++) {
                float4 af = *(const float4*)(VT + n * 64 + i0);
                float4 bf = *(const float4*)(Xs + n * 64 + h0);
#pragma unroll
                for (int a = 0; a < 4; a++) {
                    float av = (&af.x)[a];
                    acc[a][0] = fmaf(av, bf.x, acc[a][0]);
                    acc[a][1] = fmaf(av, bf.y, acc[a][1]);
                    acc[a][2] = fmaf(av, bf.z, acc[a][2]);
                    acc[a][3] = fmaf(av, bf.w, acc[a][3]);
                }
            }
#pragma unroll 8
            for (int j = 0; j < 64; j++) {
                float4 af = *(const float4*)(TzT + j * 64 + i0);
                float4 bf = *(const float4*)(Us + j * 64 + h0);
#pragma unroll
                for (int a = 0; a < 4; a++) {
                    float av = (&af.x)[a];
                    acc[a][0] = fmaf(av, bf.x, acc[a][0]);
                    acc[a][1] = fmaf(av, bf.y, acc[a][1]);
                    acc[a][2] = fmaf(av, bf.z, acc[a][2]);
                    acc[a][3] = fmaf(av, bf.w, acc[a][3]);
                }
            }
#pragma unroll
            for (int a = 0; a < 4; a++) {
                float4 uf = *(const float4*)(Us + (i0 + a) * 64 + h0);
                float4 o;
                o.x = fmaf(Dv, uf.x, acc[a][0]);
                o.y = fmaf(Dv, uf.y, acc[a][1]);
                o.z = fmaf(Dv, uf.z, acc[a][2]);
                o.w = fmaf(Dv, uf.w, acc[a][3]);
                *(float4*)(yb + (size_t)(tb + i0 + a) * HD + h0) = o;
            }
        }
        __syncthreads();   // all X reads done before update

        // ---- phase 2: X[n][h] += W^T * U ----
        {
            float acc[4][4];
#pragma unroll
            for (int a = 0; a < 4; a++) {
                float4 xv = *(const float4*)(Xs + (i0 + a) * 64 + h0);
                acc[a][0] = xv.x; acc[a][1] = xv.y; acc[a][2] = xv.z; acc[a][3] = xv.w;
            }
#pragma unroll 8
            for (int j = 0; j < 64; j++) {
                float4 af = *(const float4*)(Ws + j * 64 + i0);   // W[tb+j][n0..]
                float4 bf = *(const float4*)(Us + j * 64 + h0);
#pragma unroll
                for (int a = 0; a < 4; a++) {
                    float av = (&af.x)[a];
                    acc[a][0] = fmaf(av, bf.x, acc[a][0]);
                    acc[a][1] = fmaf(av, bf.y, acc[a][1]);
                    acc[a][2] = fmaf(av, bf.z, acc[a][2]);
                    acc[a][3] = fmaf(av, bf.w, acc[a][3]);
                }
            }
#pragma unroll
            for (int a = 0; a < 4; a++) {
                float4 o;
                o.x = acc[a][0]; o.y = acc[a][1]; o.z = acc[a][2]; o.w = acc[a][3];
                *(float4*)(Xs + (i0 + a) * 64 + h0) = o;
            }
        }
        __syncthreads();   // X updated before next chunk overwrites Us/Ws/VT
    }
}

extern "C" void kernel_launch(void* const* d_in, const int* in_sizes, int n_in,
                              void* d_out, int out_size) {
    const float* u     = (const float*)d_in[0];
    const float* B_ssm = (const float*)d_in[1];
    const float* C_ssm = (const float*)d_in[2];
    const float* D_skip = (const float*)d_in[3];
    const float* log_dt = (const float*)d_in[4];
    float* y = (float*)d_out;

    cudaFuncSetAttribute(setup_kernel, cudaFuncAttributeMaxDynamicSharedMemorySize, 65536);
    cudaFuncSetAttribute(main_kernel,  cudaFuncAttributeMaxDynamicSharedMemorySize, 81920);

    setup_kernel<<<1, 256, 65536>>>(B_ssm, log_dt);
    expand_kernel<<<LSEQ, 64>>>(C_ssm);
    main_kernel<<<BSZ * 8, 256, 81920>>>(u, D_skip, y);
}

// round 5
// speedup vs baseline: 1.2475x; 1.2475x over previous
#include <cuda_runtime.h>
#include <math.h>

#define LSEQ 2048
#define NST  64
#define HD   512
#define BSZ  16

// ------------- device scratch (static; no runtime allocation) -------------
__device__ float d_P[11 * 64 * 64];    // Abar^(2^k), k=0..10, row-major, lower-tri
__device__ float d_Bbar[64];
__device__ float d_W[LSEQ * 64];       // w[s][n]  = (Abar^s Bbar)[n]
__device__ float d_V[LSEQ * 64];       // v[t][n]  = (C Abar^{L-1-t})[n]
__device__ float d_K[LSEQ];            // K[l]     = C Abar^l Bbar

// ---------------- full 64x64 smem matmul, 512 threads, 2x4 reg tile ----------------
// C = A*B (row-major). Upper triangles are stored as zeros so the full product
// is exact for lower-triangular operands and keeps the zeros.
// mode 0: C[e] = acc
// mode 1: C[e] = acc*scale + I   (Horner step)
__device__ __forceinline__ void mm64(const float* __restrict__ A,
                                     const float* __restrict__ B,
                                     float* __restrict__ C,
                                     int tid, int mode, float scale) {
    int tx = tid & 15, ty = tid >> 4;        // tx 0..15, ty 0..31
    int j0 = tx << 2, i0 = ty << 1;
    float acc00 = 0.f, acc01 = 0.f, acc02 = 0.f, acc03 = 0.f;
    float acc10 = 0.f, acc11 = 0.f, acc12 = 0.f, acc13 = 0.f;
    const float* Ar0 = A + i0 * 64;
    const float* Ar1 = A + (i0 + 1) * 64;
#pragma unroll 8
    for (int k = 0; k < 64; k++) {
        float a0 = Ar0[k];
        float a1 = Ar1[k];
        float4 b = *(const float4*)(B + k * 64 + j0);
        acc00 = fmaf(a0, b.x, acc00); acc01 = fmaf(a0, b.y, acc01);
        acc02 = fmaf(a0, b.z, acc02); acc03 = fmaf(a0, b.w, acc03);
        acc10 = fmaf(a1, b.x, acc10); acc11 = fmaf(a1, b.y, acc11);
        acc12 = fmaf(a1, b.z, acc12); acc13 = fmaf(a1, b.w, acc13);
    }
    float4 o0, o1;
    if (mode == 1) {
        o0.x = acc00 * scale + ((i0    ) == (j0    ) ? 1.f : 0.f);
        o0.y = acc01 * scale + ((i0    ) == (j0 + 1) ? 1.f : 0.f);
        o0.z = acc02 * scale + ((i0    ) == (j0 + 2) ? 1.f : 0.f);
        o0.w = acc03 * scale + ((i0    ) == (j0 + 3) ? 1.f : 0.f);
        o1.x = acc10 * scale + ((i0 + 1) == (j0    ) ? 1.f : 0.f);
        o1.y = acc11 * scale + ((i0 + 1) == (j0 + 1) ? 1.f : 0.f);
        o1.z = acc12 * scale + ((i0 + 1) == (j0 + 2) ? 1.f : 0.f);
        o1.w = acc13 * scale + ((i0 + 1) == (j0 + 3) ? 1.f : 0.f);
    } else {
        o0.x = acc00; o0.y = acc01; o0.z = acc02; o0.w = acc03;
        o1.x = acc10; o1.y = acc11; o1.z = acc12; o1.w = acc13;
    }
    *(float4*)(C + i0 * 64 + j0) = o0;
    *(float4*)(C + (i0 + 1) * 64 + j0) = o1;
}

// ---------- setup: A, expm(dt*A) via scaling-squaring Taylor-12, Bbar, powers ----------
__global__ void __launch_bounds__(512, 1)
setup_kernel(const float* __restrict__ B_in, const float* __restrict__ logdt) {
    extern __shared__ float sm[];
    float* As = sm;            // original A (lower tri), 4096
    float* Xs = sm + 4096;     // scaled dt*A
    float* Ra = sm + 8192;     // ping
    float* Rb = sm + 12288;    // pong
    __shared__ float colsum[64];
    __shared__ float rhs[64], bb[64];
    __shared__ int s_sh;
    int tid = threadIdx.x;

    double dt = exp((double)logdt[0]);
    for (int e = tid; e < 4096; e += 512) {
        int i = e >> 6, j = e & 63;
        float a = 0.0f, x = 0.0f;
        if (j <= i) {
            double pij = sqrt((1.0 + 2.0 * i) * (1.0 + 2.0 * j));
            double av = pij - (i == j ? (double)i : 0.0);
            a = (float)(-av);
            x = (float)(-av * dt);
        }
        As[e] = a; Xs[e] = x;
    }
    __syncthreads();
    if (tid < 64) {                               // column 1-norms of dt*A
        float ssum = 0.0f;
        for (int i = tid; i < 64; i++) ssum += fabsf(Xs[i * 64 + tid]);
        colsum[tid] = ssum;
    }
    __syncthreads();
    if (tid == 0) {
        float mx = 0.0f;
        for (int j = 0; j < 64; j++) mx = fmaxf(mx, colsum[j]);
        int s = 0; float v = mx;
        while (v > 1.0f && s < 30) { v *= 0.5f; s++; }
        s_sh = s;
    }
    __syncthreads();
    int s = s_sh;
    float scale = ldexpf(1.0f, -s);
    for (int e = tid; e < 4096; e += 512) Xs[e] *= scale;
    __syncthreads();

    // Taylor deg-12 Horner: R = I + X/12; for k=11..1: R = I + (X*R)/k
    for (int e = tid; e < 4096; e += 512) {
        int i = e >> 6, j = e & 63;
        Ra[e] = Xs[e] * (1.0f / 12.0f) + (i == j ? 1.0f : 0.0f);
    }
    __syncthreads();
    float* cur = Ra; float* nxt = Rb;
    for (int k = 11; k >= 1; k--) {
        mm64(Xs, cur, nxt, tid, 1, 1.0f / (float)k);
        __syncthreads();
        float* t = cur; cur = nxt; nxt = t;
    }
    for (int q = 0; q < s; q++) {                 // undo scaling: s squarings
        mm64(cur, cur, nxt, tid, 0, 0.f);
        __syncthreads();
        float* t = cur; cur = nxt; nxt = t;
    }
    for (int e = tid; e < 4096; e += 512) d_P[e] = cur[e];   // P0 = Abar
    for (int k = 1; k < 11; k++) {                // Pk = P_{k-1}^2
        mm64(cur, cur, nxt, tid, 0, 0.f);
        __syncthreads();
        for (int e = tid; e < 4096; e += 512) d_P[k * 4096 + e] = nxt[e];
        float* t = cur; cur = nxt; nxt = t;
        __syncthreads();
    }
    // rhs = (Abar - I) B ; Bbar = A^{-1} rhs  (forward substitution)
    if (tid < 64) {
        float acc = 0.0f;
        const float* Abar = d_P;
        for (int j = 0; j < 64; j++) {
            float p = Abar[tid * 64 + j] - (tid == j ? 1.0f : 0.0f);
            acc = fmaf(p, B_in[j], acc);
        }
        rhs[tid] = acc;
    }
    __syncthreads();
    if (tid == 0) {
        for (int i = 0; i < 64; i++) {
            double acc = (double)rhs[i];
            for (int j = 0; j < i; j++) acc -= (double)As[i * 64 + j] * (double)bb[j];
            bb[i] = (float)(acc / (double)As[i * 64 + i]);
        }
    }
    __syncthreads();
    if (tid < 64) d_Bbar[tid] = bb[tid];
}

// ---- expand: w[s], v-row(s), K[s] via bit-product; block = s, 64 threads ----
__global__ void expand_kernel(const float* __restrict__ C_in) {
    int s = blockIdx.x;
    int t = threadIdx.x;
    __shared__ float xs[64], rs[64], prod[64];
    xs[t] = d_Bbar[t];
    rs[t] = C_in[t];
    __syncthreads();
    for (int k = 0; k < 11; k++) {
        if ((s >> k) & 1) {                        // uniform branch per block
            const float* P = d_P + k * 4096;
            float a = 0.0f, b = 0.0f;
            for (int j = 0; j <= t; j++) a = fmaf(P[t * 64 + j], xs[j], a);  // row t
            for (int i = t; i < 64; i++) b = fmaf(rs[i], P[i * 64 + t], b);  // col t
            __syncthreads();
            xs[t] = a; rs[t] = b;
            __syncthreads();
        }
    }
    d_W[s * 64 + t] = xs[t];
    d_V[(LSEQ - 1 - s) * 64 + t] = rs[t];          // v[t] = C Abar^{L-1-t}
    prod[t] = rs[t] * d_Bbar[t];
    __syncthreads();
    if (t == 0) {
        float acc = 0.0f;
        for (int j = 0; j < 64; j++) acc += prod[j];
        d_K[s] = acc;                               // K[s] = C Abar^s Bbar
    }
}

// ---------------- main fused chunked-scan kernel ----------------
// block = (b, 64-h tile). 32 sequential chunks of 64 timesteps; state X[n][h]
// lives in smem. Per chunk:
//   Y[i][h] = sum_n V[tb+i][n] X[n][h] + sum_{j<=i} K[L-1-(i-j)] U[j][h] + D U[i][h]
//   X[n][h] += sum_j W[tb+j][n] U[j][h]
__global__ void __launch_bounds__(256, 1)
main_kernel(const float* __restrict__ u, const float* __restrict__ Dp, float* __restrict__ y) {
    extern __shared__ float sm[];
    float* Us  = sm;           // [j][h]
    float* Ws  = sm + 4096;    // [j][n]
    float* VT  = sm + 8192;    // [n][i]  (V transposed)
    float* TzT = sm + 12288;   // [j][i]  TzT[j][i] = K[L-1-(i-j)], i>=j
    float* Xs  = sm + 16384;   // [n][h]  running state

    int tid = threadIdx.x;
    int b = blockIdx.x >> 3;
    int habs = (blockIdx.x & 7) << 6;
    float Dv = Dp[0];

    for (int e = tid; e < 4096; e += 256) {
        int j = e >> 6, i = e & 63;
        TzT[e] = (i >= j) ? d_K[LSEQ - 1 - (i - j)] : 0.0f;
        Xs[e] = 0.0f;
    }

    int tx = tid & 15, ty = tid >> 4;
    int h0 = tx << 2, i0 = ty << 2;

    const float* ub = u + (size_t)b * LSEQ * HD + habs;
    float*       yb = y + (size_t)b * LSEQ * HD + habs;

    for (int c = 0; c < 32; c++) {
        int tb = c << 6;
        // ---- loads ----
        for (int f = tid; f < 1024; f += 256) {    // u tile [64 x 64], coalesced
            int j = f >> 4, q = f & 15;
            ((float4*)Us)[(j << 4) + q] =
                __ldg((const float4*)(ub + (size_t)(tb + j) * HD) + q);
        }
        {
            const float4* Wg = (const float4*)(d_W + (size_t)tb * 64);
            for (int f = tid; f < 1024; f += 256) ((float4*)Ws)[f] = __ldg(Wg + f);
        }
        {   // V slice transposed: VT[n][i] = d_V[(tb+i)*64+n]
            int ii = tid & 63, ng = tid >> 6;      // 4 groups x 16 n each
            const float* Vrow = d_V + (size_t)(tb + ii) * 64 + (ng << 4);
#pragma unroll
            for (int q2 = 0; q2 < 4; q2++) {
                float4 v = *(const float4*)(Vrow + (q2 << 2));
                int n0 = (ng << 4) + (q2 << 2);
                VT[(n0 + 0) * 64 + ii] = v.x;
                VT[(n0 + 1) * 64 + ii] = v.y;
                VT[(n0 + 2) * 64 + ii] = v.z;
                VT[(n0 + 3) * 64 + ii] = v.w;
            }
        }
        __syncthreads();

        // ---- phase 1: Y = V*X + Tz*U + D*U, write to gmem ----
        {
            float acc[4][4];
#pragma unroll
            for (int a = 0; a < 4; a++)
#pragma unroll
                for (int q = 0; q < 4; q++) acc[a][q] = 0.0f;
#pragma unroll 8
            for (int n = 0; n < 64; n++) {
                float4 af = *(const float4*)(VT + n * 64 + i0);
                float4 bf = *(const float4*)(Xs + n * 64 + h0);
#pragma unroll
                for (int a = 0; a < 4; a++) {
                    float av = (&af.x)[a];
                    acc[a][0] = fmaf(av, bf.x, acc[a][0]);
                    acc[a][1] = fmaf(av, bf.y, acc[a][1]);
                    acc[a][2] = fmaf(av, bf.z, acc[a][2]);
                    acc[a][3] = fmaf(av, bf.w, acc[a][3]);
                }
            }
#pragma unroll 8
            for (int j = 0; j < 64; j++) {
                float4 af = *(const float4*)(TzT + j * 64 + i0);
                float4 bf = *(const float4*)(Us + j * 64 + h0);
#pragma unroll
                for (int a = 0; a < 4; a++) {
                    float av = (&af.x)[a];
                    acc[a][0] = fmaf(av, bf.x, acc[a][0]);
                    acc[a][1] = fmaf(av, bf.y, acc[a][1]);
                    acc[a][2] = fmaf(av, bf.z, acc[a][2]);
                    acc[a][3] = fmaf(av, bf.w, acc[a][3]);
                }
            }
#pragma unroll
            for (int a = 0; a < 4; a++) {
                float4 uf = *(const float4*)(Us + (i0 + a) * 64 + h0);
                float4 o;
                o.x = fmaf(Dv, uf.x, acc[a][0]);
                o.y = fmaf(Dv, uf.y, acc[a][1]);
                o.z = fmaf(Dv, uf.z, acc[a][2]);
                o.w = fmaf(Dv, uf.w, acc[a][3]);
                *(float4*)(yb + (size_t)(tb + i0 + a) * HD + h0) = o;
            }
        }
        __syncthreads();   // all X reads done before update

        // ---- phase 2: X[n][h] += W^T * U ----
        {
            float acc[4][4];
#pragma unroll
            for (int a = 0; a < 4; a++) {
                float4 xv = *(const float4*)(Xs + (i0 + a) * 64 + h0);
                acc[a][0] = xv.x; acc[a][1] = xv.y; acc[a][2] = xv.z; acc[a][3] = xv.w;
            }
#pragma unroll 8
            for (int j = 0; j < 64; j++) {
                float4 af = *(const float4*)(Ws + j * 64 + i0);   // W[tb+j][n0..]
                float4 bf = *(const float4*)(Us + j * 64 + h0);
#pragma unroll
                for (int a = 0; a < 4; a++) {
                    float av = (&af.x)[a];
                    acc[a][0] = fmaf(av, bf.x, acc[a][0]);
                    acc[a][1] = fmaf(av, bf.y, acc[a][1]);
                    acc[a][2] = fmaf(av, bf.z, acc[a][2]);
                    acc[a][3] = fmaf(av, bf.w, acc[a][3]);
                }
            }
#pragma unroll
            for (int a = 0; a < 4; a++) {
                float4 o;
                o.x = acc[a][0]; o.y = acc[a][1]; o.z = acc[a][2]; o.w = acc[a][3];
                *(float4*)(Xs + (i0 + a) * 64 + h0) = o;
            }
        }
        __syncthreads();   // X updated before next chunk overwrites Us/Ws/VT
    }
}

extern "C" void kernel_launch(void* const* d_in, const int* in_sizes, int n_in,
                              void* d_out, int out_size) {
    const float* u      = (const float*)d_in[0];
    const float* B_ssm  = (const float*)d_in[1];
    const float* C_ssm  = (const float*)d_in[2];
    const float* D_skip = (const float*)d_in[3];
    const float* log_dt = (const float*)d_in[4];
    float* y = (float*)d_out;

    cudaFuncSetAttribute(setup_kernel, cudaFuncAttributeMaxDynamicSharedMemorySize, 65536);
    cudaFuncSetAttribute(main_kernel,  cudaFuncAttributeMaxDynamicSharedMemorySize, 81920);

    setup_kernel<<<1, 512, 65536>>>(B_ssm, log_dt);
    expand_kernel<<<LSEQ, 64>>>(C_ssm);
    main_kernel<<<BSZ * 8, 256, 81920>>>(u, D_skip, y);
}

// round 6
// speedup vs baseline: 2.2288x; 1.7867x over previous
#include <cuda_runtime.h>
#include <math.h>
#include <stdint.h>

#define LSEQ 2048
#define HD   512
#define BSZ  16

// ------------- device scratch (static; no runtime allocation) -------------
__device__ float d_P [11 * 4096];   // Abar^(2^k), k=0..10, row-major
__device__ float d_PT[11 * 4096];   // transposes
__device__ float d_Bbar[64];
__device__ float d_W0 [64 * 64];    // w_j (j<64) rows
__device__ float d_Vr0[64 * 64];    // vrev_r = C Abar^r (r<64) rows
__device__ float d_W[LSEQ * 64];    // w[s][n]
__device__ float d_V[LSEQ * 64];    // v[t][n] = C Abar^{L-1-t}

// =============== packed f32x2 helpers ===============
__device__ __forceinline__ uint64_t dup2(float x) {
    uint64_t r; uint32_t u = __float_as_uint(x);
    asm("mov.b64 %0, {%1, %1};" : "=l"(r) : "r"(u));
    return r;
}
__device__ __forceinline__ void fma2(uint64_t& d, uint64_t a, uint64_t b) {
    asm("fma.rn.f32x2 %0, %1, %2, %0;" : "+l"(d) : "l"(a), "l"(b));
}

// =============== setup: fast 64x64 matmul with transposed copies ===============
// C = A*B. AT[k][i]=A[i][k] enables float4 loads on both operands.
// Writes C and CT. mode1: out = acc*scale + I (Horner step).
__device__ __forceinline__ void mm64T(const float* __restrict__ AT, const float* __restrict__ B,
                                      float* __restrict__ C, float* __restrict__ CT,
                                      int tid, int mode, float scale) {
    int tx = tid & 15, ty = tid >> 4;
    int j0 = tx << 2, i0 = ty << 2;
    float acc[4][4];
#pragma unroll
    for (int a = 0; a < 4; a++)
#pragma unroll
        for (int q = 0; q < 4; q++) acc[a][q] = 0.f;
#pragma unroll 8
    for (int k = 0; k < 64; k++) {
        float4 av = *(const float4*)(AT + k * 64 + i0);
        float4 bv = *(const float4*)(B  + k * 64 + j0);
#pragma unroll
        for (int a = 0; a < 4; a++) {
            float aa = (&av.x)[a];
            acc[a][0] = fmaf(aa, bv.x, acc[a][0]);
            acc[a][1] = fmaf(aa, bv.y, acc[a][1]);
            acc[a][2] = fmaf(aa, bv.z, acc[a][2]);
            acc[a][3] = fmaf(aa, bv.w, acc[a][3]);
        }
    }
#pragma unroll
    for (int a = 0; a < 4; a++) {
        float4 o;
#pragma unroll
        for (int q = 0; q < 4; q++) {
            float v = acc[a][q];
            if (mode == 1) v = v * scale + ((i0 + a) == (j0 + q) ? 1.f : 0.f);
            (&o.x)[q] = v;
        }
        *(float4*)(C + (i0 + a) * 64 + j0) = o;
    }
#pragma unroll
    for (int q = 0; q < 4; q++) {
        float4 o;
#pragma unroll
        for (int a = 0; a < 4; a++) {
            float v = acc[a][q];
            if (mode == 1) v = v * scale + ((i0 + a) == (j0 + q) ? 1.f : 0.f);
            (&o.x)[a] = v;
        }
        *(float4*)(CT + (j0 + q) * 64 + i0) = o;
    }
}

__global__ void __launch_bounds__(256, 1)
setup_kernel(const float* __restrict__ B_in, const float* __restrict__ logdt) {
    extern __shared__ float sm[];
    float* As  = sm;            // A (lower tri)
    float* Xs  = sm + 4096;     // dt*A scaled
    float* XsT = sm + 8192;
    float* R0  = sm + 12288;
    float* R0T = sm + 16384;
    float* R1  = sm + 20480;
    float* R1T = sm + 24576;
    __shared__ float colsum[64], rhs[64], bbsh[64], bsh[64];
    __shared__ int s_sh;
    int tid = threadIdx.x;

    double dt = exp((double)logdt[0]);
    for (int e = tid; e < 4096; e += 256) {
        int i = e >> 6, j = e & 63;
        float a = 0.f, x = 0.f;
        if (j <= i) {
            double pij = sqrt((1.0 + 2.0 * i) * (1.0 + 2.0 * j));
            double av = pij - (i == j ? (double)i : 0.0);
            a = (float)(-av);
            x = (float)(-av * dt);
        }
        As[e] = a; Xs[e] = x;
        XsT[(j << 6) + i] = x;
    }
    if (tid < 64) bsh[tid] = B_in[tid];
    __syncthreads();
    if (tid < 64) {
        float ssum = 0.f;
        for (int i = tid; i < 64; i++) ssum += fabsf(Xs[i * 64 + tid]);
        colsum[tid] = ssum;
    }
    __syncthreads();
    if (tid == 0) {
        float mx = 0.f;
        for (int j = 0; j < 64; j++) mx = fmaxf(mx, colsum[j]);
        int s = 0; float v = mx;
        while (v > 1.0f && s < 30) { v *= 0.5f; s++; }
        s_sh = s;
    }
    __syncthreads();
    int s = s_sh;
    float scale = ldexpf(1.0f, -s);
    for (int e = tid; e < 4096; e += 256) { Xs[e] *= scale; XsT[e] *= scale; }
    __syncthreads();

    // Taylor deg-12 Horner: R = I + X/12; for k=11..1: R = I + (X*R)/k
    for (int e = tid; e < 4096; e += 256) {
        int i = e >> 6, j = e & 63;
        float d = (i == j) ? 1.f : 0.f;
        R0[e]  = Xs[e]  * (1.f / 12.f) + d;
        R0T[e] = XsT[e] * (1.f / 12.f) + d;
    }
    __syncthreads();
    float *cur = R0, *curT = R0T, *nxt = R1, *nxtT = R1T;
    for (int k = 11; k >= 1; k--) {
        mm64T(XsT, cur, nxt, nxtT, tid, 1, 1.f / (float)k);
        __syncthreads();
        float* t;
        t = cur; cur = nxt; nxt = t;
        t = curT; curT = nxtT; nxtT = t;
    }
    for (int q = 0; q < s; q++) {                 // undo scaling
        mm64T(curT, cur, nxt, nxtT, tid, 0, 0.f);
        __syncthreads();
        float* t;
        t = cur; cur = nxt; nxt = t;
        t = curT; curT = nxtT; nxtT = t;
    }
    // cur = Abar. rhs = (Abar - I) B  (while Abar still in smem)
    if (tid < 64) {
        float acc = 0.f;
        for (int j = 0; j < 64; j++) {
            float p = cur[tid * 64 + j] - (tid == j ? 1.f : 0.f);
            acc = fmaf(p, bsh[j], acc);
        }
        rhs[tid] = acc;
    }
    __syncthreads();
    // P0 = Abar; Pk = P_{k-1}^2
    for (int e = tid; e < 4096; e += 256) { d_P[e] = cur[e]; d_PT[e] = curT[e]; }
    for (int k = 1; k < 11; k++) {
        mm64T(curT, cur, nxt, nxtT, tid, 0, 0.f);
        __syncthreads();
        for (int e = tid; e < 4096; e += 256) {
            d_P [k * 4096 + e] = nxt[e];
            d_PT[k * 4096 + e] = nxtT[e];
        }
        float* t;
        t = cur; cur = nxt; nxt = t;
        t = curT; curT = nxtT; nxtT = t;
        __syncthreads();
    }
    // Bbar = A^{-1} rhs : parallel forward substitution (column sweep)
    float accv = (tid < 64) ? rhs[tid] : 0.f;
    for (int j = 0; j < 64; j++) {
        if (tid == j) bbsh[j] = accv / As[j * 64 + j];
        __syncthreads();
        if (tid < 64 && tid > j) accv = fmaf(-As[tid * 64 + j], bbsh[j], accv);
        __syncthreads();
    }
    if (tid < 64) d_Bbar[tid] = bbsh[tid];
}

// =============== stage A: Krylov doubling for first 64 w / vrev ===============
// block 0: W0 rows w_j = Abar^j Bbar   (w_{j+2^k} = P_k w_j  -> B-operand PT_k)
// block 1: Vr0 rows vr_r = C Abar^r    (vr_{r+2^k} = vr_r P_k -> B-operand P_k)
__global__ void __launch_bounds__(256, 1)
stageA_kernel(const float* __restrict__ C_in) {
    __shared__ float M[4096];
    __shared__ float Pb[4096];
    int tid = threadIdx.x;
    int isW = (blockIdx.x == 0);
    if (tid < 64) M[tid] = isW ? d_Bbar[tid] : C_in[tid];
    for (int k = 0; k < 6; k++) {
        const float* src = (isW ? d_PT : d_P) + k * 4096;
        __syncthreads();
        for (int f = tid; f < 1024; f += 256)
            ((float4*)Pb)[f] = __ldg((const float4*)src + f);
        __syncthreads();
        int half = 1 << k;
        for (int idx = tid; idx < half * 16; idx += 256) {
            int row = idx >> 4, n0 = (idx & 15) << 2;
            float4 acc = make_float4(0.f, 0.f, 0.f, 0.f);
            for (int m = 0; m < 64; m++) {
                float w = M[row * 64 + m];
                float4 p = *(const float4*)(Pb + m * 64 + n0);
                acc.x = fmaf(w, p.x, acc.x);
                acc.y = fmaf(w, p.y, acc.y);
                acc.z = fmaf(w, p.z, acc.z);
                acc.w = fmaf(w, p.w, acc.w);
            }
            *(float4*)(M + (half + row) * 64 + n0) = acc;
        }
    }
    __syncthreads();
    float* dst = isW ? d_W0 : d_Vr0;
    for (int f = tid; f < 1024; f += 256) ((float4*)dst)[f] = ((const float4*)M)[f];
}

// =============== chunk kernel: Q_c = Abar^{64c}; W_c, V_c GEMMs ===============
// generic 64x64 GEMM: out[(row0 + rowstep*i)*64 + j] = sum_k A[i][k] B[k][j]
__device__ __forceinline__ void mmg(const float* __restrict__ A, const float* __restrict__ B,
                                    float* __restrict__ out, int row0, int rowstep, int tid) {
    int tx = tid & 15, ty = tid >> 4;
    int j0 = tx << 2, i0 = ty << 2;
    float acc[4][4];
#pragma unroll
    for (int a = 0; a < 4; a++)
#pragma unroll
        for (int q = 0; q < 4; q++) acc[a][q] = 0.f;
#pragma unroll 8
    for (int k = 0; k < 64; k++) {
        float a0 = A[(i0 + 0) * 64 + k];
        float a1 = A[(i0 + 1) * 64 + k];
        float a2 = A[(i0 + 2) * 64 + k];
        float a3 = A[(i0 + 3) * 64 + k];
        float4 bv = *(const float4*)(B + k * 64 + j0);
        acc[0][0] = fmaf(a0, bv.x, acc[0][0]); acc[0][1] = fmaf(a0, bv.y, acc[0][1]);
        acc[0][2] = fmaf(a0, bv.z, acc[0][2]); acc[0][3] = fmaf(a0, bv.w, acc[0][3]);
        acc[1][0] = fmaf(a1, bv.x, acc[1][0]); acc[1][1] = fmaf(a1, bv.y, acc[1][1]);
        acc[1][2] = fmaf(a1, bv.z, acc[1][2]); acc[1][3] = fmaf(a1, bv.w, acc[1][3]);
        acc[2][0] = fmaf(a2, bv.x, acc[2][0]); acc[2][1] = fmaf(a2, bv.y, acc[2][1]);
        acc[2][2] = fmaf(a2, bv.z, acc[2][2]); acc[2][3] = fmaf(a2, bv.w, acc[2][3]);
        acc[3][0] = fmaf(a3, bv.x, acc[3][0]); acc[3][1] = fmaf(a3, bv.y, acc[3][1]);
        acc[3][2] = fmaf(a3, bv.z, acc[3][2]); acc[3][3] = fmaf(a3, bv.w, acc[3][3]);
    }
#pragma unroll
    for (int a = 0; a < 4; a++) {
        float4 o; o.x = acc[a][0]; o.y = acc[a][1]; o.z = acc[a][2]; o.w = acc[a][3];
        *(float4*)(out + (size_t)(row0 + rowstep * (i0 + a)) * 64 + j0) = o;
    }
}

__global__ void __launch_bounds__(256, 1)
chunk_kernel() {
    extern __shared__ float cs[];
    float* W0s  = cs;
    float* Vr0s = cs + 4096;
    float* Qa   = cs + 8192;
    float* Qb   = cs + 12288;
    float* QT   = cs + 16384;
    float* Pb   = cs + 20480;
    int tid = threadIdx.x;
    int c = blockIdx.x;

    for (int f = tid; f < 1024; f += 256) {
        ((float4*)W0s)[f]  = __ldg((const float4*)d_W0 + f);
        ((float4*)Vr0s)[f] = __ldg((const float4*)d_Vr0 + f);
    }
    __syncthreads();

    if (c == 0) {
        // W rows 0..63 = W0 ; V rows: t = 2047 - r
        for (int f = tid; f < 1024; f += 256) ((float4*)d_W)[f] = ((const float4*)W0s)[f];
        for (int e = tid; e < 4096; e += 256) {
            int r = e >> 6, n = e & 63;
            d_V[(size_t)(2047 - r) * 64 + n] = Vr0s[e];
        }
        return;
    }

    // build Q_c = product of P_{6+k} over set bits of c (powers commute)
    int bits = c;
    int k0 = __ffs(bits) - 1; bits &= bits - 1;
    for (int f = tid; f < 1024; f += 256)
        ((float4*)Qa)[f] = __ldg((const float4*)(d_P + (6 + k0) * 4096) + f);
    float *qcur = Qa, *qnxt = Qb;
    while (bits) {
        int k = __ffs(bits) - 1; bits &= bits - 1;
        __syncthreads();
        for (int f = tid; f < 1024; f += 256)
            ((float4*)Pb)[f] = __ldg((const float4*)(d_P + (6 + k) * 4096) + f);
        __syncthreads();
        mmg(qcur, Pb, qnxt, 0, 1, tid);         // Q <- Q * P
        float* t = qcur; qcur = qnxt; qnxt = t;
    }
    __syncthreads();
    // QT
    for (int e = tid; e < 4096; e += 256) {
        int i = e >> 6, j = e & 63;
        QT[j * 64 + i] = qcur[e];
    }
    __syncthreads();
    // W_c[j][n] = sum_m W0[j][m] QT[m][n]  -> d_W rows 64c+j
    mmg(W0s, QT, d_W, 64 * c, 1, tid);
    // Vr_c[r][n] = sum_m Vr0[r][m] Q[m][n] -> d_V rows 2047-64c-r
    mmg(Vr0s, qcur, d_V, 2047 - 64 * c, -1, tid);
}

// =============== main fused chunked-scan kernel (packed f32x2) ===============
__global__ void __launch_bounds__(256, 1)
main_kernel(const float* __restrict__ u, const float* __restrict__ Dp, float* __restrict__ y) {
    extern __shared__ float sm[];
    float* Us  = sm;           // [j][h]
    float* Ws  = sm + 4096;    // [j][n]
    float* VT  = sm + 8192;    // [n][i]
    float* TzT = sm + 12288;   // [j][i] = K[2047-(i-j)] for i>=j else 0
    float* Xs  = sm + 16384;   // [n][h] running state

    int tid = threadIdx.x;
    int b = blockIdx.x >> 3;
    int habs = (blockIdx.x & 7) << 6;
    float Dv = Dp[0];
    uint64_t dv2 = dup2(Dv);

    for (int e = tid; e < 4096; e += 256) Xs[e] = 0.f;

    int tx = tid & 15, ty = tid >> 4;
    int h0 = tx << 2, i0 = ty << 2;

    const float* ub = u + (size_t)b * LSEQ * HD + habs;
    float*       yb = y + (size_t)b * LSEQ * HD + habs;

    for (int c = 0; c < 32; c++) {
        int tb = c << 6;
        // ---- loads ----
        for (int f = tid; f < 1024; f += 256) {
            int j = f >> 4, q = f & 15;
            ((float4*)Us)[(j << 4) + q] =
                __ldg((const float4*)(ub + (size_t)(tb + j) * HD) + q);
        }
        {
            const float4* Wg = (const float4*)(d_W + (size_t)tb * 64);
            for (int f = tid; f < 1024; f += 256) ((float4*)Ws)[f] = __ldg(Wg + f);
        }
        {   // VT[n][i] = d_V[(tb+i)*64+n]
            int ii = tid & 63, ng = tid >> 6;
            const float* Vrow = d_V + (size_t)(tb + ii) * 64 + (ng << 4);
#pragma unroll
            for (int q2 = 0; q2 < 4; q2++) {
                float4 v = *(const float4*)(Vrow + (q2 << 2));
                int n0 = (ng << 4) + (q2 << 2);
                VT[(n0 + 0) * 64 + ii] = v.x;
                VT[(n0 + 1) * 64 + ii] = v.y;
                VT[(n0 + 2) * 64 + ii] = v.z;
                VT[(n0 + 3) * 64 + ii] = v.w;
            }
        }
        __syncthreads();

        if (c == 0) {
            // TzT[j][i] = dot(v_i, w_j) masked to i>=j  (j rows = ty, i cols = tx)
            int jj0 = ty << 2, ii0 = tx << 2;
            float acc[4][4];
#pragma unroll
            for (int a = 0; a < 4; a++)
#pragma unroll
                for (int q = 0; q < 4; q++) acc[a][q] = 0.f;
            for (int n = 0; n < 64; n++) {
                float4 vv = *(const float4*)(VT + n * 64 + ii0);
#pragma unroll
                for (int a = 0; a < 4; a++) {
                    float w = Ws[(jj0 + a) * 64 + n];
                    acc[a][0] = fmaf(w, vv.x, acc[a][0]);
                    acc[a][1] = fmaf(w, vv.y, acc[a][1]);
                    acc[a][2] = fmaf(w, vv.z, acc[a][2]);
                    acc[a][3] = fmaf(w, vv.w, acc[a][3]);
                }
            }
#pragma unroll
            for (int a = 0; a < 4; a++) {
                float4 o;
#pragma unroll
                for (int q = 0; q < 4; q++)
                    (&o.x)[q] = (ii0 + q >= jj0 + a) ? acc[a][q] : 0.f;
                *(float4*)(TzT + (jj0 + a) * 64 + ii0) = o;
            }
            __syncthreads();
        }

        // ---- phase 1: Y = V*X + Tz*U + D*U ----
        {
            uint64_t acc[4][2];
#pragma unroll
            for (int a = 0; a < 4; a++) { acc[a][0] = 0ull; acc[a][1] = 0ull; }
#pragma unroll 8
            for (int n = 0; n < 64; n++) {
                float4 af = *(const float4*)(VT + n * 64 + i0);
                ulonglong2 bv = *(const ulonglong2*)(Xs + n * 64 + h0);
#pragma unroll
                for (int a = 0; a < 4; a++) {
                    uint64_t ad = dup2((&af.x)[a]);
                    fma2(acc[a][0], ad, bv.x);
                    fma2(acc[a][1], ad, bv.y);
                }
            }
#pragma unroll 8
            for (int j = 0; j < 64; j++) {
                float4 af = *(const float4*)(TzT + j * 64 + i0);
                ulonglong2 bv = *(const ulonglong2*)(Us + j * 64 + h0);
#pragma unroll
                for (int a = 0; a < 4; a++) {
                    uint64_t ad = dup2((&af.x)[a]);
                    fma2(acc[a][0], ad, bv.x);
                    fma2(acc[a][1], ad, bv.y);
                }
            }
#pragma unroll
            for (int a = 0; a < 4; a++) {
                ulonglong2 uv = *(const ulonglong2*)(Us + (i0 + a) * 64 + h0);
                fma2(acc[a][0], dv2, uv.x);
                fma2(acc[a][1], dv2, uv.y);
                ulonglong2 o; o.x = acc[a][0]; o.y = acc[a][1];
                *(ulonglong2*)(yb + (size_t)(tb + i0 + a) * HD + h0) = o;
            }
        }
        __syncthreads();   // all X reads done before update

        // ---- phase 2: X[n][h] += W^T * U ----
        {
            uint64_t acc[4][2];
#pragma unroll
            for (int a = 0; a < 4; a++) {
                ulonglong2 xv = *(const ulonglong2*)(Xs + (i0 + a) * 64 + h0);
                acc[a][0] = xv.x; acc[a][1] = xv.y;
            }
#pragma unroll 8
            for (int j = 0; j < 64; j++) {
                float4 af = *(const float4*)(Ws + j * 64 + i0);
                ulonglong2 bv = *(const ulonglong2*)(Us + j * 64 + h0);
#pragma unroll
                for (int a = 0; a < 4; a++) {
                    uint64_t ad = dup2((&af.x)[a]);
                    fma2(acc[a][0], ad, bv.x);
                    fma2(acc[a][1], ad, bv.y);
                }
            }
#pragma unroll
            for (int a = 0; a < 4; a++) {
                ulonglong2 o; o.x = acc[a][0]; o.y = acc[a][1];
                *(ulonglong2*)(Xs + (i0 + a) * 64 + h0) = o;
            }
        }
        __syncthreads();
    }
}

extern "C" void kernel_launch(void* const* d_in, const int* in_sizes, int n_in,
                              void* d_out, int out_size) {
    const float* u      = (const float*)d_in[0];
    const float* B_ssm  = (const float*)d_in[1];
    const float* C_ssm  = (const float*)d_in[2];
    const float* D_skip = (const float*)d_in[3];
    const float* log_dt = (const float*)d_in[4];
    float* y = (float*)d_out;

    cudaFuncSetAttribute(setup_kernel, cudaFuncAttributeMaxDynamicSharedMemorySize, 114688);
    cudaFuncSetAttribute(chunk_kernel, cudaFuncAttributeMaxDynamicSharedMemorySize, 98304);
    cudaFuncSetAttribute(main_kernel,  cudaFuncAttributeMaxDynamicSharedMemorySize, 81920);

    setup_kernel<<<1, 256, 114688>>>(B_ssm, log_dt);
    stageA_kernel<<<2, 256>>>(C_ssm);
    chunk_kernel<<<32, 256, 98304>>>();
    main_kernel<<<BSZ * 8, 256, 81920>>>(u, D_skip, y);
}